// round 1
// baseline (speedup 1.0000x reference)
#include <cuda_runtime.h>
#include <math.h>

#define Bz 256
#define Sz 256
#define Mz 50
#define DQz 64
#define DVz 128
#define Fz 128
#define NQ1 10001
#define NQA1 20001
#define NROWS (Bz*Sz)

// Scratch (static device globals — no allocation allowed)
__device__ float g_w[NQ1 * Mz];        // softmax weights per unique q index
__device__ float g_er[NQA1 * DVz];     // erase per unique qa index
__device__ float g_ad[NQA1 * DVz];     // add per unique qa index
__device__ float g_reads[NROWS * DVz]; // scan outputs
__device__ float g_acc[2];             // [0]=bce sum, [1]=mask count

// ---------------------------------------------------------------------------
__global__ void k_init() {
    if (threadIdx.x < 2) g_acc[threadIdx.x] = 0.0f;
}

// ---------------------------------------------------------------------------
// w[i,m] = softmax_m( q_table[i] . key_mem[m] )  for all 10001 unique q rows
__global__ void k_w(const float* __restrict__ q_table,
                    const float* __restrict__ key_mem) {
    __shared__ float key_s[Mz * DQz];
    int tid = threadIdx.x;
    for (int i = tid; i < Mz * DQz; i += blockDim.x) key_s[i] = key_mem[i];
    __syncthreads();

    int row = blockIdx.x * 128 + tid;
    if (row >= NQ1) return;

    float q[DQz];
    const float4* qp = (const float4*)(q_table + row * DQz);
#pragma unroll
    for (int i = 0; i < DQz / 4; i++) {
        float4 v = qp[i];
        q[4*i+0] = v.x; q[4*i+1] = v.y; q[4*i+2] = v.z; q[4*i+3] = v.w;
    }

    float sc[Mz];
    float mx = -1e30f;
#pragma unroll
    for (int m = 0; m < Mz; m++) {
        float s = 0.0f;
#pragma unroll
        for (int k = 0; k < DQz; k++) s = fmaf(q[k], key_s[m * DQz + k], s);
        sc[m] = s;
        mx = fmaxf(mx, s);
    }
    float sum = 0.0f;
#pragma unroll
    for (int m = 0; m < Mz; m++) {
        float e = __expf(sc[m] - mx);
        sc[m] = e;
        sum += e;
    }
    float inv = 1.0f / sum;
#pragma unroll
    for (int m = 0; m < Mz; m++) g_w[row * Mz + m] = sc[m] * inv;
}

// ---------------------------------------------------------------------------
// erase/add tables for all 20001 unique qa rows:
//   er[i,:] = sigmoid(qa_table[i] @ W_e + b_e), ad[i,:] = tanh(qa_table[i] @ W_a + b_a)
#define EA_SMEM_FLOATS (16384 + 16384 + 16*DVz + 128 + 128)
__global__ void k_ea(const float* __restrict__ qa_table,
                     const float* __restrict__ W_e, const float* __restrict__ b_e,
                     const float* __restrict__ W_a, const float* __restrict__ b_a) {
    extern __shared__ float sm[];
    float* We = sm;                 // 128x128
    float* Wa = We + 16384;         // 128x128
    float* xs = Wa + 16384;         // 16 rows x 128
    float* be = xs + 16 * DVz;
    float* ba = be + 128;

    int tid = threadIdx.x;
    for (int i = tid; i < 16384; i += 256) { We[i] = W_e[i]; Wa[i] = W_a[i]; }
    if (tid < 128) { be[tid] = b_e[tid]; ba[tid] = b_a[tid]; }

    int row0 = blockIdx.x * 16;
    for (int idx = tid; idx < 16 * 32; idx += 256) {
        int r = idx >> 5, c = idx & 31;
        int row = row0 + r;
        float4 v = make_float4(0.f, 0.f, 0.f, 0.f);
        if (row < NQA1) v = ((const float4*)(qa_table + (long)row * DVz))[c];
        ((float4*)xs)[r * 32 + c] = v;
    }
    __syncthreads();

    int rg = tid >> 4;   // row within tile (16 rows, 16 threads each)
    int fg = tid & 15;   // 8 output columns each
    int row = row0 + rg;
    float ae[8], aa[8];
#pragma unroll
    for (int j = 0; j < 8; j++) { ae[j] = 0.f; aa[j] = 0.f; }

#pragma unroll 4
    for (int k = 0; k < DVz; k++) {
        float xv = xs[rg * DVz + k];
        const float4* wep = (const float4*)(We + k * DVz + fg * 8);
        const float4* wap = (const float4*)(Wa + k * DVz + fg * 8);
        float4 e0 = wep[0], e1 = wep[1];
        float4 a0 = wap[0], a1 = wap[1];
        ae[0]=fmaf(xv,e0.x,ae[0]); ae[1]=fmaf(xv,e0.y,ae[1]);
        ae[2]=fmaf(xv,e0.z,ae[2]); ae[3]=fmaf(xv,e0.w,ae[3]);
        ae[4]=fmaf(xv,e1.x,ae[4]); ae[5]=fmaf(xv,e1.y,ae[5]);
        ae[6]=fmaf(xv,e1.z,ae[6]); ae[7]=fmaf(xv,e1.w,ae[7]);
        aa[0]=fmaf(xv,a0.x,aa[0]); aa[1]=fmaf(xv,a0.y,aa[1]);
        aa[2]=fmaf(xv,a0.z,aa[2]); aa[3]=fmaf(xv,a0.w,aa[3]);
        aa[4]=fmaf(xv,a1.x,aa[4]); aa[5]=fmaf(xv,a1.y,aa[5]);
        aa[6]=fmaf(xv,a1.z,aa[6]); aa[7]=fmaf(xv,a1.w,aa[7]);
    }

    if (row < NQA1) {
#pragma unroll
        for (int j = 0; j < 8; j++) {
            int f = fg * 8 + j;
            g_er[(long)row * DVz + f] = 1.0f / (1.0f + __expf(-(ae[j] + be[f])));
            g_ad[(long)row * DVz + f] = tanhf(aa[j] + ba[f]);
        }
    }
}

// ---------------------------------------------------------------------------
// Sequential scan: one block per batch, 128 threads (one per DV lane),
// memory state mem[50] in registers per thread.
__global__ void __launch_bounds__(DVz) k_scan(const int* __restrict__ q_data,
                                              const int* __restrict__ qa_data,
                                              const float* __restrict__ init_value) {
    __shared__ float w_s[2][Mz];
    int b = blockIdx.x;
    int d = threadIdx.x;

    float mem[Mz];
#pragma unroll
    for (int m = 0; m < Mz; m++) mem[m] = init_value[m * DVz + d];

    int base = b * Sz;
    if (d < Mz) w_s[0][d] = g_w[q_data[base] * Mz + d];
    __syncthreads();

    int buf = 0;
    for (int s = 0; s < Sz; s++) {
        int bs = base + s;
        int qai = qa_data[bs];
        float e = g_er[(long)qai * DVz + d];
        float a = g_ad[(long)qai * DVz + d];
        bool flag = (q_data[bs] >= 1);

        // prefetch next step's w into the other buffer
        if (s + 1 < Sz && d < Mz) w_s[buf ^ 1][d] = g_w[q_data[bs + 1] * Mz + d];

        // read = sum_m w[m] * mem[m]
        float r0 = 0.f, r1 = 0.f, r2 = 0.f, r3 = 0.f;
#pragma unroll
        for (int m = 0; m < 48; m += 4) {
            r0 = fmaf(w_s[buf][m + 0], mem[m + 0], r0);
            r1 = fmaf(w_s[buf][m + 1], mem[m + 1], r1);
            r2 = fmaf(w_s[buf][m + 2], mem[m + 2], r2);
            r3 = fmaf(w_s[buf][m + 3], mem[m + 3], r3);
        }
        r0 = fmaf(w_s[buf][48], mem[48], r0);
        r1 = fmaf(w_s[buf][49], mem[49], r1);
        g_reads[(long)bs * DVz + d] = (r0 + r1) + (r2 + r3);

        if (flag) {
#pragma unroll
            for (int m = 0; m < Mz; m++) {
                float wm = w_s[buf][m];
                float t = wm * e;
                float p = fmaf(wm, a, mem[m]);   // mem + w*add
                mem[m] = fmaf(-t, mem[m], p);     // - w*erase*mem
            }
        }
        __syncthreads();
        buf ^= 1;
    }
}

// ---------------------------------------------------------------------------
// Head: h = tanh([reads, q_emb] @ W_read + b_read); logit = h @ W_pred + b_pred;
// probs + masked BCE accumulation.
#define HEAD_SMEM_FLOATS (192*128 + 64*192 + 128 + 128 + 64 + 2)
__global__ void k_head(const int* __restrict__ q_data,
                       const float* __restrict__ target,
                       const float* __restrict__ q_table,
                       const float* __restrict__ W_read, const float* __restrict__ b_read,
                       const float* __restrict__ W_pred, const float* __restrict__ b_pred,
                       float* __restrict__ out) {
    extern __shared__ float sm[];
    float* Ws = sm;                   // 192 x 128
    float* xs = Ws + 192 * 128;       // 64 rows x 192
    float* br = xs + 64 * 192;        // 128
    float* wp = br + 128;             // 128
    float* lo = wp + 128;             // 64 logits
    float* ls = lo + 64;              // bce sum, count

    int tid = threadIdx.x;
    for (int i = tid; i < 192 * 128; i += 256) Ws[i] = W_read[i];
    if (tid < 128) { br[tid] = b_read[tid]; wp[tid] = W_pred[tid]; }
    if (tid < 64)  lo[tid] = b_pred[0];
    if (tid < 2)   ls[tid] = 0.0f;

    int row0 = blockIdx.x * 64;
    // Load x tile: cols [0,128) = reads, [128,192) = q_emb gather
    for (int idx = tid; idx < 64 * 48; idx += 256) {
        int r = idx / 48, c = idx % 48;
        int row = row0 + r;
        float4 v;
        if (c < 32) {
            v = ((const float4*)(g_reads + (long)row * DVz))[c];
        } else {
            int qi = q_data[row];
            v = ((const float4*)(q_table + (long)qi * DQz))[c - 32];
        }
        ((float4*)(xs + r * 192))[c] = v;
    }
    __syncthreads();

    int rg = tid >> 4;  // 16 groups x 4 rows
    int fg = tid & 15;  // 16 groups x 8 f-cols
    float acc[4][8];
#pragma unroll
    for (int r = 0; r < 4; r++)
#pragma unroll
        for (int j = 0; j < 8; j++) acc[r][j] = 0.0f;

#pragma unroll 4
    for (int k = 0; k < 192; k++) {
        const float4* wv = (const float4*)(Ws + k * 128 + fg * 8);
        float4 w0 = wv[0], w1 = wv[1];
#pragma unroll
        for (int r = 0; r < 4; r++) {
            float xv = xs[(rg * 4 + r) * 192 + k];
            acc[r][0]=fmaf(xv,w0.x,acc[r][0]); acc[r][1]=fmaf(xv,w0.y,acc[r][1]);
            acc[r][2]=fmaf(xv,w0.z,acc[r][2]); acc[r][3]=fmaf(xv,w0.w,acc[r][3]);
            acc[r][4]=fmaf(xv,w1.x,acc[r][4]); acc[r][5]=fmaf(xv,w1.y,acc[r][5]);
            acc[r][6]=fmaf(xv,w1.z,acc[r][6]); acc[r][7]=fmaf(xv,w1.w,acc[r][7]);
        }
    }

#pragma unroll
    for (int r = 0; r < 4; r++) {
        float p = 0.0f;
#pragma unroll
        for (int j = 0; j < 8; j++) {
            int f = fg * 8 + j;
            float h = tanhf(acc[r][j] + br[f]);
            p = fmaf(h, wp[f], p);
        }
        atomicAdd(&lo[rg * 4 + r], p);
    }
    __syncthreads();

    if (tid < 64) {
        int row = row0 + tid;
        float l = lo[tid];
        float prob = 1.0f / (1.0f + __expf(-l));
        out[1 + row] = prob;
        float t = target[row];
        if (t >= 0.0f) {
            float bce = fmaxf(l, 0.0f) - l * t + log1pf(__expf(-fabsf(l)));
            atomicAdd(&ls[0], bce);
            atomicAdd(&ls[1], 1.0f);
        }
    }
    __syncthreads();
    if (tid == 0) {
        atomicAdd(&g_acc[0], ls[0]);
        atomicAdd(&g_acc[1], ls[1]);
    }
}

// ---------------------------------------------------------------------------
__global__ void k_fin(float* __restrict__ out) {
    out[0] = g_acc[0] / fmaxf(g_acc[1], 1.0f);
}

// ---------------------------------------------------------------------------
extern "C" void kernel_launch(void* const* d_in, const int* in_sizes, int n_in,
                              void* d_out, int out_size) {
    const int*   q_data    = (const int*)d_in[0];
    const int*   qa_data   = (const int*)d_in[1];
    const float* target    = (const float*)d_in[2];
    const float* q_table   = (const float*)d_in[3];
    const float* qa_table  = (const float*)d_in[4];
    const float* key_mem   = (const float*)d_in[5];
    const float* init_value= (const float*)d_in[6];
    const float* W_e    = (const float*)d_in[7];
    const float* b_e    = (const float*)d_in[8];
    const float* W_a    = (const float*)d_in[9];
    const float* b_a    = (const float*)d_in[10];
    const float* W_read = (const float*)d_in[11];
    const float* b_read = (const float*)d_in[12];
    const float* W_pred = (const float*)d_in[13];
    const float* b_pred = (const float*)d_in[14];
    float* out = (float*)d_out;

    cudaFuncSetAttribute(k_ea, cudaFuncAttributeMaxDynamicSharedMemorySize,
                         EA_SMEM_FLOATS * (int)sizeof(float));
    cudaFuncSetAttribute(k_head, cudaFuncAttributeMaxDynamicSharedMemorySize,
                         HEAD_SMEM_FLOATS * (int)sizeof(float));

    k_init<<<1, 32>>>();
    k_w<<<(NQ1 + 127) / 128, 128>>>(q_table, key_mem);
    k_ea<<<(NQA1 + 15) / 16, 256, EA_SMEM_FLOATS * sizeof(float)>>>(qa_table, W_e, b_e, W_a, b_a);
    k_scan<<<Bz, DVz>>>(q_data, qa_data, init_value);
    k_head<<<NROWS / 64, 256, HEAD_SMEM_FLOATS * sizeof(float)>>>(
        q_data, target, q_table, W_read, b_read, W_pred, b_pred, out);
    k_fin<<<1, 1>>>(out);
}

// round 2
// speedup vs baseline: 1.2610x; 1.2610x over previous
#include <cuda_runtime.h>
#include <math.h>

#define Bz 256
#define Sz 256
#define Mz 50
#define DQz 64
#define DVz 128
#define Fz 128
#define NQ1 10001
#define NQA1 20001
#define NROWS (Bz*Sz)

// Scratch (static device globals — no allocation allowed)
__device__ float g_w[NQ1 * Mz];        // softmax weights per unique q index
__device__ float g_er[NQA1 * DVz];     // erase per unique qa index
__device__ float g_ad[NQA1 * DVz];     // add per unique qa index
__device__ float g_reads[NROWS * DVz]; // scan outputs
__device__ float g_acc[2];             // [0]=bce sum, [1]=mask count

// ---------------------------------------------------------------------------
__global__ void k_init() {
    if (threadIdx.x < 2) g_acc[threadIdx.x] = 0.0f;
}

// ---------------------------------------------------------------------------
// w[i,m] = softmax_m( q_table[i] . key_mem[m] )  for all 10001 unique q rows
__global__ void k_w(const float* __restrict__ q_table,
                    const float* __restrict__ key_mem) {
    __shared__ float key_s[Mz * DQz];
    int tid = threadIdx.x;
    for (int i = tid; i < Mz * DQz; i += blockDim.x) key_s[i] = key_mem[i];
    __syncthreads();

    int row = blockIdx.x * 128 + tid;
    if (row >= NQ1) return;

    float q[DQz];
    const float4* qp = (const float4*)(q_table + row * DQz);
#pragma unroll
    for (int i = 0; i < DQz / 4; i++) {
        float4 v = qp[i];
        q[4*i+0] = v.x; q[4*i+1] = v.y; q[4*i+2] = v.z; q[4*i+3] = v.w;
    }

    float sc[Mz];
    float mx = -1e30f;
#pragma unroll
    for (int m = 0; m < Mz; m++) {
        float s = 0.0f;
#pragma unroll
        for (int k = 0; k < DQz; k++) s = fmaf(q[k], key_s[m * DQz + k], s);
        sc[m] = s;
        mx = fmaxf(mx, s);
    }
    float sum = 0.0f;
#pragma unroll
    for (int m = 0; m < Mz; m++) {
        float e = __expf(sc[m] - mx);
        sc[m] = e;
        sum += e;
    }
    float inv = 1.0f / sum;
#pragma unroll
    for (int m = 0; m < Mz; m++) g_w[row * Mz + m] = sc[m] * inv;
}

// ---------------------------------------------------------------------------
// erase/add tables for all 20001 unique qa rows. 64 rows per block, 512 thr.
#define EA_ROWS 64
#define EA_SMEM_FLOATS (16384 + 16384 + EA_ROWS*DVz + 128 + 128)
__global__ void __launch_bounds__(512) k_ea(const float* __restrict__ qa_table,
                     const float* __restrict__ W_e, const float* __restrict__ b_e,
                     const float* __restrict__ W_a, const float* __restrict__ b_a) {
    extern __shared__ float sm[];
    float* We = sm;                     // 128x128
    float* Wa = We + 16384;             // 128x128
    float* xs = Wa + 16384;             // 64 rows x 128
    float* be = xs + EA_ROWS * DVz;
    float* ba = be + 128;

    int tid = threadIdx.x;
    // stage weights (float4)
    for (int i = tid; i < 4096; i += 512) {
        ((float4*)We)[i] = ((const float4*)W_e)[i];
        ((float4*)Wa)[i] = ((const float4*)W_a)[i];
    }
    if (tid < 128) { be[tid] = b_e[tid]; ba[tid] = b_a[tid]; }

    int row0 = blockIdx.x * EA_ROWS;
    for (int idx = tid; idx < EA_ROWS * 32; idx += 512) {
        int r = idx >> 5, c = idx & 31;
        int row = row0 + r;
        float4 v = make_float4(0.f, 0.f, 0.f, 0.f);
        if (row < NQA1) v = ((const float4*)(qa_table + (long)row * DVz))[c];
        ((float4*)xs)[r * 32 + c] = v;
    }
    __syncthreads();

    int rg = tid >> 4;   // 32 groups of 2 rows
    int fg = tid & 15;   // 8 output columns each
    float ae[2][8], aa[2][8];
#pragma unroll
    for (int r = 0; r < 2; r++)
#pragma unroll
        for (int j = 0; j < 8; j++) { ae[r][j] = 0.f; aa[r][j] = 0.f; }

#pragma unroll 4
    for (int k = 0; k < DVz; k++) {
        const float4* wep = (const float4*)(We + k * DVz + fg * 8);
        const float4* wap = (const float4*)(Wa + k * DVz + fg * 8);
        float4 e0 = wep[0], e1 = wep[1];
        float4 a0 = wap[0], a1 = wap[1];
#pragma unroll
        for (int r = 0; r < 2; r++) {
            float xv = xs[(rg * 2 + r) * DVz + k];
            ae[r][0]=fmaf(xv,e0.x,ae[r][0]); ae[r][1]=fmaf(xv,e0.y,ae[r][1]);
            ae[r][2]=fmaf(xv,e0.z,ae[r][2]); ae[r][3]=fmaf(xv,e0.w,ae[r][3]);
            ae[r][4]=fmaf(xv,e1.x,ae[r][4]); ae[r][5]=fmaf(xv,e1.y,ae[r][5]);
            ae[r][6]=fmaf(xv,e1.z,ae[r][6]); ae[r][7]=fmaf(xv,e1.w,ae[r][7]);
            aa[r][0]=fmaf(xv,a0.x,aa[r][0]); aa[r][1]=fmaf(xv,a0.y,aa[r][1]);
            aa[r][2]=fmaf(xv,a0.z,aa[r][2]); aa[r][3]=fmaf(xv,a0.w,aa[r][3]);
            aa[r][4]=fmaf(xv,a1.x,aa[r][4]); aa[r][5]=fmaf(xv,a1.y,aa[r][5]);
            aa[r][6]=fmaf(xv,a1.z,aa[r][6]); aa[r][7]=fmaf(xv,a1.w,aa[r][7]);
        }
    }

#pragma unroll
    for (int r = 0; r < 2; r++) {
        int row = row0 + rg * 2 + r;
        if (row < NQA1) {
            float er8[8], ad8[8];
#pragma unroll
            for (int j = 0; j < 8; j++) {
                int f = fg * 8 + j;
                er8[j] = 1.0f / (1.0f + __expf(-(ae[r][j] + be[f])));
                ad8[j] = tanhf(aa[r][j] + ba[f]);
            }
            float4* ep = (float4*)(g_er + (long)row * DVz + fg * 8);
            float4* ap = (float4*)(g_ad + (long)row * DVz + fg * 8);
            ep[0] = make_float4(er8[0], er8[1], er8[2], er8[3]);
            ep[1] = make_float4(er8[4], er8[5], er8[6], er8[7]);
            ap[0] = make_float4(ad8[0], ad8[1], ad8[2], ad8[3]);
            ap[1] = make_float4(ad8[4], ad8[5], ad8[6], ad8[7]);
        }
    }
}

// ---------------------------------------------------------------------------
// Sequential scan: one block per batch, 512 threads = 4 M-groups x 128 DV.
// Each thread owns 13 memory slots in registers. One barrier per step.
#define MG 13
__global__ void __launch_bounds__(512) k_scan(const int* __restrict__ q_data,
                                              const int* __restrict__ qa_data,
                                              const float* __restrict__ init_value) {
    __shared__ float w_s[2][56];
    __shared__ float red[2][4][DVz];
    __shared__ int qi_s[Sz];
    __shared__ int qai_s[Sz];

    int b = blockIdx.x;
    int tid = threadIdx.x;
    int d = tid & 127;
    int g = tid >> 7;        // 0..3
    int m0 = g * MG;         // 0,13,26,39

    int base = b * Sz;
    for (int i = tid; i < Sz; i += 512) {
        qi_s[i]  = q_data[base + i];
        qai_s[i] = qa_data[base + i];
    }

    float mem[MG];
#pragma unroll
    for (int i = 0; i < MG; i++) {
        int m = m0 + i;
        mem[i] = (m < Mz) ? init_value[m * DVz + d] : 0.0f;
    }
    __syncthreads();

    // prime pipeline: w + e/a for step 0
    if (tid < Mz) w_s[0][tid] = g_w[qi_s[0] * Mz + tid];
    int qa0 = qai_s[0];
    float en = g_er[qa0 * DVz + d];
    float an = g_ad[qa0 * DVz + d];
    __syncthreads();

    int buf = 0;
    for (int s = 0; s < Sz; s++) {
        float e = en, a = an;
        // prefetch next step (hides L2 latency behind compute)
        if (s + 1 < Sz) {
            int qan = qai_s[s + 1];
            en = g_er[qan * DVz + d];
            an = g_ad[qan * DVz + d];
            if (tid < Mz) w_s[buf ^ 1][tid] = g_w[qi_s[s + 1] * Mz + tid];
        }

        // partial read over this group's slots
        float wr[MG];
        float pr = 0.0f;
#pragma unroll
        for (int i = 0; i < MG; i++) {
            int m = m0 + i;
            if (m < Mz) {
                wr[i] = w_s[buf][m];
                pr = fmaf(wr[i], mem[i], pr);
            }
        }
        red[buf][g][d] = pr;

        // update owned slots (uses current-step w/e/a; independent of barrier)
        if (qi_s[s] >= 1) {
#pragma unroll
            for (int i = 0; i < MG; i++) {
                int m = m0 + i;
                if (m < Mz) {
                    float wm = wr[i];
                    float t = wm * e;
                    float p = fmaf(wm, a, mem[i]);
                    mem[i] = fmaf(-t, mem[i], p);
                }
            }
        }

        __syncthreads();
        if (g == 0) {
            float tot = (red[buf][0][d] + red[buf][1][d]) +
                        (red[buf][2][d] + red[buf][3][d]);
            g_reads[(long)(base + s) * DVz + d] = tot;
        }
        buf ^= 1;
    }
}

// ---------------------------------------------------------------------------
// Head: 128-row tiles, 512 threads. Shuffle-reduced logits, no shared atomics
// on the hot path.
#define HD_ROWS 128
#define HEAD_SMEM_FLOATS (192*128 + HD_ROWS*192 + 128 + 128 + HD_ROWS + 2)
__global__ void __launch_bounds__(512) k_head(const int* __restrict__ q_data,
                       const float* __restrict__ target,
                       const float* __restrict__ q_table,
                       const float* __restrict__ W_read, const float* __restrict__ b_read,
                       const float* __restrict__ W_pred, const float* __restrict__ b_pred,
                       float* __restrict__ out) {
    extern __shared__ float sm[];
    float* Ws = sm;                   // 192 x 128
    float* xs = Ws + 192 * 128;       // 128 rows x 192
    float* br = xs + HD_ROWS * 192;   // 128
    float* wp = br + 128;             // 128
    float* lo = wp + 128;             // 128 logits
    float* ls = lo + HD_ROWS;         // bce sum, count

    int tid = threadIdx.x;
    for (int i = tid; i < 192 * 128 / 4; i += 512)
        ((float4*)Ws)[i] = ((const float4*)W_read)[i];
    if (tid < 128) { br[tid] = b_read[tid]; wp[tid] = W_pred[tid]; }
    if (tid < 2)   ls[tid] = 0.0f;

    int row0 = blockIdx.x * HD_ROWS;
    // x tile: cols [0,128) = reads, [128,192) = q_emb gather
    for (int idx = tid; idx < HD_ROWS * 48; idx += 512) {
        int r = idx / 48, c = idx % 48;
        int row = row0 + r;
        float4 v;
        if (c < 32) {
            v = ((const float4*)(g_reads + (long)row * DVz))[c];
        } else {
            int qi = q_data[row];
            v = ((const float4*)(q_table + (long)qi * DQz))[c - 32];
        }
        ((float4*)(xs + r * 192))[c] = v;
    }
    __syncthreads();

    int rg = tid >> 4;  // 32 groups x 4 rows
    int fg = tid & 15;  // 16 groups x 8 f-cols
    float acc[4][8];
#pragma unroll
    for (int r = 0; r < 4; r++)
#pragma unroll
        for (int j = 0; j < 8; j++) acc[r][j] = 0.0f;

#pragma unroll 4
    for (int k = 0; k < 192; k++) {
        const float4* wv = (const float4*)(Ws + k * 128 + fg * 8);
        float4 w0 = wv[0], w1 = wv[1];
#pragma unroll
        for (int r = 0; r < 4; r++) {
            float xv = xs[(rg * 4 + r) * 192 + k];
            acc[r][0]=fmaf(xv,w0.x,acc[r][0]); acc[r][1]=fmaf(xv,w0.y,acc[r][1]);
            acc[r][2]=fmaf(xv,w0.z,acc[r][2]); acc[r][3]=fmaf(xv,w0.w,acc[r][3]);
            acc[r][4]=fmaf(xv,w1.x,acc[r][4]); acc[r][5]=fmaf(xv,w1.y,acc[r][5]);
            acc[r][6]=fmaf(xv,w1.z,acc[r][6]); acc[r][7]=fmaf(xv,w1.w,acc[r][7]);
        }
    }

    float bp = __ldg(b_pred);
#pragma unroll
    for (int r = 0; r < 4; r++) {
        float p = 0.0f;
#pragma unroll
        for (int j = 0; j < 8; j++) {
            int f = fg * 8 + j;
            float h = tanhf(acc[r][j] + br[f]);
            p = fmaf(h, wp[f], p);
        }
        // reduce over the 16 fg lanes (they are consecutive lanes in a warp)
#pragma unroll
        for (int off = 8; off >= 1; off >>= 1)
            p += __shfl_down_sync(0xffffffffu, p, off, 16);
        if (fg == 0) lo[rg * 4 + r] = p + bp;
    }
    __syncthreads();

    if (tid < HD_ROWS) {
        int row = row0 + tid;
        float l = lo[tid];
        float prob = 1.0f / (1.0f + __expf(-l));
        out[1 + row] = prob;
        float t = target[row];
        float bce = 0.0f, cnt = 0.0f;
        if (t >= 0.0f) {
            bce = fmaxf(l, 0.0f) - l * t + log1pf(__expf(-fabsf(l)));
            cnt = 1.0f;
        }
        // warp-reduce then one atomic per warp
#pragma unroll
        for (int off = 16; off >= 1; off >>= 1) {
            bce += __shfl_down_sync(0xffffffffu, bce, off);
            cnt += __shfl_down_sync(0xffffffffu, cnt, off);
        }
        if ((tid & 31) == 0) {
            atomicAdd(&ls[0], bce);
            atomicAdd(&ls[1], cnt);
        }
    }
    __syncthreads();
    if (tid == 0) {
        atomicAdd(&g_acc[0], ls[0]);
        atomicAdd(&g_acc[1], ls[1]);
    }
}

// ---------------------------------------------------------------------------
__global__ void k_fin(float* __restrict__ out) {
    out[0] = g_acc[0] / fmaxf(g_acc[1], 1.0f);
}

// ---------------------------------------------------------------------------
extern "C" void kernel_launch(void* const* d_in, const int* in_sizes, int n_in,
                              void* d_out, int out_size) {
    const int*   q_data    = (const int*)d_in[0];
    const int*   qa_data   = (const int*)d_in[1];
    const float* target    = (const float*)d_in[2];
    const float* q_table   = (const float*)d_in[3];
    const float* qa_table  = (const float*)d_in[4];
    const float* key_mem   = (const float*)d_in[5];
    const float* init_value= (const float*)d_in[6];
    const float* W_e    = (const float*)d_in[7];
    const float* b_e    = (const float*)d_in[8];
    const float* W_a    = (const float*)d_in[9];
    const float* b_a    = (const float*)d_in[10];
    const float* W_read = (const float*)d_in[11];
    const float* b_read = (const float*)d_in[12];
    const float* W_pred = (const float*)d_in[13];
    const float* b_pred = (const float*)d_in[14];
    float* out = (float*)d_out;

    cudaFuncSetAttribute(k_ea, cudaFuncAttributeMaxDynamicSharedMemorySize,
                         EA_SMEM_FLOATS * (int)sizeof(float));
    cudaFuncSetAttribute(k_head, cudaFuncAttributeMaxDynamicSharedMemorySize,
                         HEAD_SMEM_FLOATS * (int)sizeof(float));

    k_init<<<1, 32>>>();
    k_w<<<(NQ1 + 127) / 128, 128>>>(q_table, key_mem);
    k_ea<<<(NQA1 + EA_ROWS - 1) / EA_ROWS, 512, EA_SMEM_FLOATS * sizeof(float)>>>(
        qa_table, W_e, b_e, W_a, b_a);
    k_scan<<<Bz, 512>>>(q_data, qa_data, init_value);
    k_head<<<NROWS / HD_ROWS, 512, HEAD_SMEM_FLOATS * sizeof(float)>>>(
        q_data, target, q_table, W_read, b_read, W_pred, b_pred, out);
    k_fin<<<1, 1>>>(out);
}

// round 3
// speedup vs baseline: 1.3478x; 1.0688x over previous
#include <cuda_runtime.h>
#include <math.h>

#define Bz 256
#define Sz 256
#define Mz 50
#define DQz 64
#define DVz 128
#define Fz 128
#define NQ1 10001
#define NQA1 20001
#define NROWS (Bz*Sz)

typedef unsigned long long u64;

// ---- packed f32x2 helpers (sm_103a FFMA2 path, PTX-only) -------------------
__device__ __forceinline__ u64 pack2(float lo, float hi) {
    u64 r; asm("mov.b64 %0, {%1, %2};" : "=l"(r) : "f"(lo), "f"(hi)); return r;
}
__device__ __forceinline__ void unpack2(u64 v, float& lo, float& hi) {
    asm("mov.b64 {%0, %1}, %2;" : "=f"(lo), "=f"(hi) : "l"(v));
}
__device__ __forceinline__ u64 fma2(u64 a, u64 b, u64 c) {
    u64 d; asm("fma.rn.f32x2 %0, %1, %2, %3;" : "=l"(d) : "l"(a), "l"(b), "l"(c)); return d;
}
__device__ __forceinline__ u64 add2(u64 a, u64 b) {
    u64 d; asm("add.rn.f32x2 %0, %1, %2;" : "=l"(d) : "l"(a), "l"(b)); return d;
}

// Scratch (static device globals — no allocation allowed)
__device__ float g_w[NQ1 * Mz];
__device__ float g_er[NQA1 * DVz];
__device__ float g_ad[NQA1 * DVz];
__device__ float g_reads[NROWS * DVz];
__device__ float g_acc[2];

// ---------------------------------------------------------------------------
__global__ void k_init() {
    if (threadIdx.x < 2) g_acc[threadIdx.x] = 0.0f;
}

// ---------------------------------------------------------------------------
__global__ void k_w(const float* __restrict__ q_table,
                    const float* __restrict__ key_mem) {
    __shared__ float key_s[Mz * DQz];
    int tid = threadIdx.x;
    for (int i = tid; i < Mz * DQz; i += blockDim.x) key_s[i] = key_mem[i];
    __syncthreads();

    int row = blockIdx.x * 128 + tid;
    if (row >= NQ1) return;

    float q[DQz];
    const float4* qp = (const float4*)(q_table + row * DQz);
#pragma unroll
    for (int i = 0; i < DQz / 4; i++) {
        float4 v = qp[i];
        q[4*i+0] = v.x; q[4*i+1] = v.y; q[4*i+2] = v.z; q[4*i+3] = v.w;
    }

    float sc[Mz];
    float mx = -1e30f;
#pragma unroll
    for (int m = 0; m < Mz; m++) {
        float s = 0.0f;
#pragma unroll
        for (int k = 0; k < DQz; k++) s = fmaf(q[k], key_s[m * DQz + k], s);
        sc[m] = s;
        mx = fmaxf(mx, s);
    }
    float sum = 0.0f;
#pragma unroll
    for (int m = 0; m < Mz; m++) {
        float e = __expf(sc[m] - mx);
        sc[m] = e;
        sum += e;
    }
    float inv = 1.0f / sum;
#pragma unroll
    for (int m = 0; m < Mz; m++) g_w[row * Mz + m] = sc[m] * inv;
}

// ---------------------------------------------------------------------------
// erase/add tables, f32x2 math. 64 rows/block, 512 threads.
#define EA_ROWS 64
#define EA_SMEM_FLOATS (16384 + 16384 + EA_ROWS*DVz + 128 + 128)
__global__ void __launch_bounds__(512) k_ea(const float* __restrict__ qa_table,
                     const float* __restrict__ W_e, const float* __restrict__ b_e,
                     const float* __restrict__ W_a, const float* __restrict__ b_a) {
    extern __shared__ float sm[];
    float* We = sm;
    float* Wa = We + 16384;
    float* xs = Wa + 16384;
    float* be = xs + EA_ROWS * DVz;
    float* ba = be + 128;

    int tid = threadIdx.x;
    for (int i = tid; i < 4096; i += 512) {
        ((float4*)We)[i] = ((const float4*)W_e)[i];
        ((float4*)Wa)[i] = ((const float4*)W_a)[i];
    }
    if (tid < 128) { be[tid] = b_e[tid]; ba[tid] = b_a[tid]; }

    int row0 = blockIdx.x * EA_ROWS;
    for (int idx = tid; idx < EA_ROWS * 32; idx += 512) {
        int r = idx >> 5, c = idx & 31;
        int row = row0 + r;
        float4 v = make_float4(0.f, 0.f, 0.f, 0.f);
        if (row < NQA1) v = ((const float4*)(qa_table + (long)row * DVz))[c];
        ((float4*)xs)[r * 32 + c] = v;
    }
    __syncthreads();

    int rg = tid >> 4;   // 32 groups of 2 rows
    int fg = tid & 15;   // 8 output cols each (4 packed pairs)
    u64 ae[2][4], aa[2][4];
#pragma unroll
    for (int r = 0; r < 2; r++)
#pragma unroll
        for (int j = 0; j < 4; j++) { ae[r][j] = 0ull; aa[r][j] = 0ull; }

#pragma unroll 4
    for (int k = 0; k < DVz; k++) {
        const ulonglong2* wep = (const ulonglong2*)(We + k * DVz + fg * 8);
        const ulonglong2* wap = (const ulonglong2*)(Wa + k * DVz + fg * 8);
        ulonglong2 e01 = wep[0], e23 = wep[1];
        ulonglong2 a01 = wap[0], a23 = wap[1];
#pragma unroll
        for (int r = 0; r < 2; r++) {
            float xv = xs[(rg * 2 + r) * DVz + k];
            u64 xp = pack2(xv, xv);
            ae[r][0] = fma2(xp, e01.x, ae[r][0]);
            ae[r][1] = fma2(xp, e01.y, ae[r][1]);
            ae[r][2] = fma2(xp, e23.x, ae[r][2]);
            ae[r][3] = fma2(xp, e23.y, ae[r][3]);
            aa[r][0] = fma2(xp, a01.x, aa[r][0]);
            aa[r][1] = fma2(xp, a01.y, aa[r][1]);
            aa[r][2] = fma2(xp, a23.x, aa[r][2]);
            aa[r][3] = fma2(xp, a23.y, aa[r][3]);
        }
    }

#pragma unroll
    for (int r = 0; r < 2; r++) {
        int row = row0 + rg * 2 + r;
        if (row < NQA1) {
            float er8[8], ad8[8];
#pragma unroll
            for (int j = 0; j < 4; j++) {
                int f = fg * 8 + 2 * j;
                float s0, s1, t0, t1;
                unpack2(ae[r][j], s0, s1);
                unpack2(aa[r][j], t0, t1);
                er8[2*j+0] = 1.0f / (1.0f + __expf(-(s0 + be[f])));
                er8[2*j+1] = 1.0f / (1.0f + __expf(-(s1 + be[f+1])));
                ad8[2*j+0] = tanhf(t0 + ba[f]);
                ad8[2*j+1] = tanhf(t1 + ba[f+1]);
            }
            float4* ep = (float4*)(g_er + (long)row * DVz + fg * 8);
            float4* ap = (float4*)(g_ad + (long)row * DVz + fg * 8);
            ep[0] = make_float4(er8[0], er8[1], er8[2], er8[3]);
            ep[1] = make_float4(er8[4], er8[5], er8[6], er8[7]);
            ap[0] = make_float4(ad8[0], ad8[1], ad8[2], ad8[3]);
            ap[1] = make_float4(ad8[4], ad8[5], ad8[6], ad8[7]);
        }
    }
}

// ---------------------------------------------------------------------------
// Scan: 128 blocks, 128 threads. Each block runs TWO batch chains (b, b+128)
// packed into f32x2 lanes. Thread owns d-column, all 50 slots in registers —
// no cross-thread reduction. Update: mem += w*(a - e*mem)  (2 FFMA2/slot).
#define SCAN_BLOCKS 128
__global__ void __launch_bounds__(128) k_scan(const int* __restrict__ q_data,
                                              const int* __restrict__ qa_data,
                                              const float* __restrict__ init_value) {
    __shared__ u64 w_s[2][Mz];    // raw packed w (for read)
    __shared__ u64 wm_s[2][Mz];   // flag-masked packed w (for update)
    __shared__ int qi0_s[Sz], qi1_s[Sz], qa0_s[Sz], qa1_s[Sz];

    int blk = blockIdx.x;
    int d = threadIdx.x;
    int base0 = blk * Sz;
    int base1 = (blk + SCAN_BLOCKS) * Sz;

    for (int i = d; i < Sz; i += 128) {
        qi0_s[i] = q_data[base0 + i];
        qi1_s[i] = q_data[base1 + i];
        qa0_s[i] = qa_data[base0 + i];
        qa1_s[i] = qa_data[base1 + i];
    }

    u64 mem[Mz];
#pragma unroll
    for (int m = 0; m < Mz; m++) {
        float v = init_value[m * DVz + d];
        mem[m] = pack2(v, v);
    }
    __syncthreads();

    // prime step 0
    if (d < Mz) {
        int qi0 = qi0_s[0], qi1 = qi1_s[0];
        float w0 = g_w[qi0 * Mz + d], w1 = g_w[qi1 * Mz + d];
        w_s[0][d]  = pack2(w0, w1);
        wm_s[0][d] = pack2(qi0 >= 1 ? w0 : 0.0f, qi1 >= 1 ? w1 : 0.0f);
    }
    float e0n = g_er[qa0_s[0] * DVz + d];
    float e1n = g_er[qa1_s[0] * DVz + d];
    float a0n = g_ad[qa0_s[0] * DVz + d];
    float a1n = g_ad[qa1_s[0] * DVz + d];
    __syncthreads();

    int buf = 0;
    for (int s = 0; s < Sz; s++) {
        u64 ne = pack2(e0n, e1n) ^ 0x8000000080000000ull;  // -e packed
        u64 av = pack2(a0n, a1n);

        // prefetch next step (hides L2 latency behind FMA issue)
        if (s + 1 < Sz) {
            int qa0 = qa0_s[s + 1], qa1 = qa1_s[s + 1];
            e0n = g_er[qa0 * DVz + d];
            e1n = g_er[qa1 * DVz + d];
            a0n = g_ad[qa0 * DVz + d];
            a1n = g_ad[qa1 * DVz + d];
            if (d < Mz) {
                int qi0 = qi0_s[s + 1], qi1 = qi1_s[s + 1];
                float w0 = g_w[qi0 * Mz + d], w1 = g_w[qi1 * Mz + d];
                w_s[buf ^ 1][d]  = pack2(w0, w1);
                wm_s[buf ^ 1][d] = pack2(qi0 >= 1 ? w0 : 0.0f, qi1 >= 1 ? w1 : 0.0f);
            }
        }

        // read: r[d] = sum_m w[m]*mem[m]  (both batches in packed lanes)
        u64 r0 = 0ull, r1 = 0ull, r2 = 0ull, r3 = 0ull;
#pragma unroll
        for (int m = 0; m < 48; m += 4) {
            r0 = fma2(w_s[buf][m + 0], mem[m + 0], r0);
            r1 = fma2(w_s[buf][m + 1], mem[m + 1], r1);
            r2 = fma2(w_s[buf][m + 2], mem[m + 2], r2);
            r3 = fma2(w_s[buf][m + 3], mem[m + 3], r3);
        }
        r0 = fma2(w_s[buf][48], mem[48], r0);
        r1 = fma2(w_s[buf][49], mem[49], r1);
        u64 rr = add2(add2(r0, r1), add2(r2, r3));
        float lo, hi;
        unpack2(rr, lo, hi);
        g_reads[(long)(base0 + s) * DVz + d] = lo;
        g_reads[(long)(base1 + s) * DVz + d] = hi;

        // update: mem += w_masked * (a - e*mem)   [masked half => unchanged]
#pragma unroll
        for (int m = 0; m < Mz; m++) {
            u64 t = fma2(ne, mem[m], av);
            mem[m] = fma2(wm_s[buf][m], t, mem[m]);
        }

        __syncthreads();
        buf ^= 1;
    }
}

// ---------------------------------------------------------------------------
// Head: 128-row tiles, 512 threads, f32x2 accumulation.
#define HD_ROWS 128
#define HEAD_SMEM_FLOATS (192*128 + HD_ROWS*192 + 128 + 128 + HD_ROWS + 2)
__global__ void __launch_bounds__(512) k_head(const int* __restrict__ q_data,
                       const float* __restrict__ target,
                       const float* __restrict__ q_table,
                       const float* __restrict__ W_read, const float* __restrict__ b_read,
                       const float* __restrict__ W_pred, const float* __restrict__ b_pred,
                       float* __restrict__ out) {
    extern __shared__ float sm[];
    float* Ws = sm;                   // 192 x 128
    float* xs = Ws + 192 * 128;       // 128 rows x 192
    float* br = xs + HD_ROWS * 192;
    float* wp = br + 128;
    float* lo = wp + 128;
    float* ls = lo + HD_ROWS;

    int tid = threadIdx.x;
    for (int i = tid; i < 192 * 128 / 4; i += 512)
        ((float4*)Ws)[i] = ((const float4*)W_read)[i];
    if (tid < 128) { br[tid] = b_read[tid]; wp[tid] = W_pred[tid]; }
    if (tid < 2)   ls[tid] = 0.0f;

    int row0 = blockIdx.x * HD_ROWS;
    for (int idx = tid; idx < HD_ROWS * 48; idx += 512) {
        int r = idx / 48, c = idx % 48;
        int row = row0 + r;
        float4 v;
        if (c < 32) {
            v = ((const float4*)(g_reads + (long)row * DVz))[c];
        } else {
            int qi = q_data[row];
            v = ((const float4*)(q_table + (long)qi * DQz))[c - 32];
        }
        ((float4*)(xs + r * 192))[c] = v;
    }
    __syncthreads();

    int rg = tid >> 4;  // 32 groups x 4 rows
    int fg = tid & 15;  // 16 groups x 8 f-cols (4 packed pairs)
    u64 acc[4][4];
#pragma unroll
    for (int r = 0; r < 4; r++)
#pragma unroll
        for (int j = 0; j < 4; j++) acc[r][j] = 0ull;

#pragma unroll 4
    for (int k = 0; k < 192; k++) {
        const ulonglong2* wv = (const ulonglong2*)(Ws + k * 128 + fg * 8);
        ulonglong2 w01 = wv[0], w23 = wv[1];
#pragma unroll
        for (int r = 0; r < 4; r++) {
            float xv = xs[(rg * 4 + r) * 192 + k];
            u64 xp = pack2(xv, xv);
            acc[r][0] = fma2(xp, w01.x, acc[r][0]);
            acc[r][1] = fma2(xp, w01.y, acc[r][1]);
            acc[r][2] = fma2(xp, w23.x, acc[r][2]);
            acc[r][3] = fma2(xp, w23.y, acc[r][3]);
        }
    }

    float bp = __ldg(b_pred);
#pragma unroll
    for (int r = 0; r < 4; r++) {
        float p = 0.0f;
#pragma unroll
        for (int j = 0; j < 4; j++) {
            int f = fg * 8 + 2 * j;
            float s0, s1;
            unpack2(acc[r][j], s0, s1);
            p = fmaf(tanhf(s0 + br[f]),     wp[f],     p);
            p = fmaf(tanhf(s1 + br[f + 1]), wp[f + 1], p);
        }
#pragma unroll
        for (int off = 8; off >= 1; off >>= 1)
            p += __shfl_down_sync(0xffffffffu, p, off, 16);
        if (fg == 0) lo[rg * 4 + r] = p + bp;
    }
    __syncthreads();

    if (tid < HD_ROWS) {
        int row = row0 + tid;
        float l = lo[tid];
        float prob = 1.0f / (1.0f + __expf(-l));
        out[1 + row] = prob;
        float t = target[row];
        float bce = 0.0f, cnt = 0.0f;
        if (t >= 0.0f) {
            bce = fmaxf(l, 0.0f) - l * t + log1pf(__expf(-fabsf(l)));
            cnt = 1.0f;
        }
#pragma unroll
        for (int off = 16; off >= 1; off >>= 1) {
            bce += __shfl_down_sync(0xffffffffu, bce, off);
            cnt += __shfl_down_sync(0xffffffffu, cnt, off);
        }
        if ((tid & 31) == 0) {
            atomicAdd(&ls[0], bce);
            atomicAdd(&ls[1], cnt);
        }
    }
    __syncthreads();
    if (tid == 0) {
        atomicAdd(&g_acc[0], ls[0]);
        atomicAdd(&g_acc[1], ls[1]);
    }
}

// ---------------------------------------------------------------------------
__global__ void k_fin(float* __restrict__ out) {
    out[0] = g_acc[0] / fmaxf(g_acc[1], 1.0f);
}

// ---------------------------------------------------------------------------
extern "C" void kernel_launch(void* const* d_in, const int* in_sizes, int n_in,
                              void* d_out, int out_size) {
    const int*   q_data    = (const int*)d_in[0];
    const int*   qa_data   = (const int*)d_in[1];
    const float* target    = (const float*)d_in[2];
    const float* q_table   = (const float*)d_in[3];
    const float* qa_table  = (const float*)d_in[4];
    const float* key_mem   = (const float*)d_in[5];
    const float* init_value= (const float*)d_in[6];
    const float* W_e    = (const float*)d_in[7];
    const float* b_e    = (const float*)d_in[8];
    const float* W_a    = (const float*)d_in[9];
    const float* b_a    = (const float*)d_in[10];
    const float* W_read = (const float*)d_in[11];
    const float* b_read = (const float*)d_in[12];
    const float* W_pred = (const float*)d_in[13];
    const float* b_pred = (const float*)d_in[14];
    float* out = (float*)d_out;

    cudaFuncSetAttribute(k_ea, cudaFuncAttributeMaxDynamicSharedMemorySize,
                         EA_SMEM_FLOATS * (int)sizeof(float));
    cudaFuncSetAttribute(k_head, cudaFuncAttributeMaxDynamicSharedMemorySize,
                         HEAD_SMEM_FLOATS * (int)sizeof(float));

    k_init<<<1, 32>>>();
    k_w<<<(NQ1 + 127) / 128, 128>>>(q_table, key_mem);
    k_ea<<<(NQA1 + EA_ROWS - 1) / EA_ROWS, 512, EA_SMEM_FLOATS * sizeof(float)>>>(
        qa_table, W_e, b_e, W_a, b_a);
    k_scan<<<SCAN_BLOCKS, 128>>>(q_data, qa_data, init_value);
    k_head<<<NROWS / HD_ROWS, 512, HEAD_SMEM_FLOATS * sizeof(float)>>>(
        q_data, target, q_table, W_read, b_read, W_pred, b_pred, out);
    k_fin<<<1, 1>>>(out);
}

// round 4
// speedup vs baseline: 1.6377x; 1.2152x over previous
#include <cuda_runtime.h>
#include <math.h>

#define Bz 256
#define Sz 256
#define Mz 50
#define MP 25          // slot pairs
#define DQz 64
#define DVz 128
#define Fz 128
#define NQ1 10001
#define NQA1 20001
#define NROWS (Bz*Sz)

typedef unsigned long long u64;

// ---- packed f32x2 helpers (sm_103a FFMA2 path, PTX-only) -------------------
__device__ __forceinline__ u64 pack2(float lo, float hi) {
    u64 r; asm("mov.b64 %0, {%1, %2};" : "=l"(r) : "f"(lo), "f"(hi)); return r;
}
__device__ __forceinline__ void unpack2(u64 v, float& lo, float& hi) {
    asm("mov.b64 {%0, %1}, %2;" : "=f"(lo), "=f"(hi) : "l"(v));
}
__device__ __forceinline__ u64 fma2(u64 a, u64 b, u64 c) {
    u64 d; asm("fma.rn.f32x2 %0, %1, %2, %3;" : "=l"(d) : "l"(a), "l"(b), "l"(c)); return d;
}
__device__ __forceinline__ u64 add2(u64 a, u64 b) {
    u64 d; asm("add.rn.f32x2 %0, %1, %2;" : "=l"(d) : "l"(a), "l"(b)); return d;
}

// Scratch (static device globals — no allocation allowed)
__device__ float g_w[NQ1 * Mz];
__device__ float g_er[NQA1 * DVz];
__device__ float g_ad[NQA1 * DVz];
__device__ float g_qr[NQ1 * Fz];       // q_emb @ W_read[128:192] per unique q
__device__ float g_reads[NROWS * DVz];
__device__ float g_acc[2];

// ---------------------------------------------------------------------------
__global__ void k_init() {
    if (threadIdx.x < 2) g_acc[threadIdx.x] = 0.0f;
}

// ---------------------------------------------------------------------------
__global__ void k_w(const float* __restrict__ q_table,
                    const float* __restrict__ key_mem) {
    __shared__ float key_s[Mz * DQz];
    int tid = threadIdx.x;
    for (int i = tid; i < Mz * DQz; i += blockDim.x) key_s[i] = key_mem[i];
    __syncthreads();

    int row = blockIdx.x * 128 + tid;
    if (row >= NQ1) return;

    float q[DQz];
    const float4* qp = (const float4*)(q_table + row * DQz);
#pragma unroll
    for (int i = 0; i < DQz / 4; i++) {
        float4 v = qp[i];
        q[4*i+0] = v.x; q[4*i+1] = v.y; q[4*i+2] = v.z; q[4*i+3] = v.w;
    }

    float sc[Mz];
    float mx = -1e30f;
#pragma unroll
    for (int m = 0; m < Mz; m++) {
        float s = 0.0f;
#pragma unroll
        for (int k = 0; k < DQz; k++) s = fmaf(q[k], key_s[m * DQz + k], s);
        sc[m] = s;
        mx = fmaxf(mx, s);
    }
    float sum = 0.0f;
#pragma unroll
    for (int m = 0; m < Mz; m++) {
        float e = __expf(sc[m] - mx);
        sc[m] = e;
        sum += e;
    }
    float inv = 1.0f / sum;
#pragma unroll
    for (int m = 0; m < Mz; m++) g_w[row * Mz + m] = sc[m] * inv;
}

// ---------------------------------------------------------------------------
// q-part of the head: g_qr[i,:] = q_table[i,:] @ W_read[128:192,:]
#define QR_ROWS 64
#define QR_SMEM_FLOATS (64*128 + QR_ROWS*DQz)
__global__ void __launch_bounds__(512) k_qr(const float* __restrict__ q_table,
                                            const float* __restrict__ W_read) {
    extern __shared__ float sm[];
    float* W2 = sm;                  // 64 x 128 (rows 128..191 of W_read)
    float* xs = W2 + 64 * 128;       // 64 rows x 64

    int tid = threadIdx.x;
    for (int i = tid; i < 64 * 128 / 4; i += 512)
        ((float4*)W2)[i] = ((const float4*)(W_read + 128 * 128))[i];

    int row0 = blockIdx.x * QR_ROWS;
    for (int idx = tid; idx < QR_ROWS * 16; idx += 512) {
        int r = idx >> 4, c = idx & 15;
        int row = row0 + r;
        float4 v = make_float4(0.f, 0.f, 0.f, 0.f);
        if (row < NQ1) v = ((const float4*)(q_table + (long)row * DQz))[c];
        ((float4*)xs)[r * 16 + c] = v;
    }
    __syncthreads();

    int rg = tid >> 4;   // 32 groups of 2 rows
    int fg = tid & 15;   // 8 cols each (4 packed pairs)
    u64 acc[2][4];
#pragma unroll
    for (int r = 0; r < 2; r++)
#pragma unroll
        for (int j = 0; j < 4; j++) acc[r][j] = 0ull;

#pragma unroll 4
    for (int k = 0; k < 64; k++) {
        const ulonglong2* wv = (const ulonglong2*)(W2 + k * 128 + fg * 8);
        ulonglong2 w01 = wv[0], w23 = wv[1];
#pragma unroll
        for (int r = 0; r < 2; r++) {
            float xv = xs[(rg * 2 + r) * DQz + k];
            u64 xp = pack2(xv, xv);
            acc[r][0] = fma2(xp, w01.x, acc[r][0]);
            acc[r][1] = fma2(xp, w01.y, acc[r][1]);
            acc[r][2] = fma2(xp, w23.x, acc[r][2]);
            acc[r][3] = fma2(xp, w23.y, acc[r][3]);
        }
    }

#pragma unroll
    for (int r = 0; r < 2; r++) {
        int row = row0 + rg * 2 + r;
        if (row < NQ1) {
            float v[8];
#pragma unroll
            for (int j = 0; j < 4; j++) unpack2(acc[r][j], v[2*j], v[2*j+1]);
            float4* op = (float4*)(g_qr + (long)row * Fz + fg * 8);
            op[0] = make_float4(v[0], v[1], v[2], v[3]);
            op[1] = make_float4(v[4], v[5], v[6], v[7]);
        }
    }
}

// ---------------------------------------------------------------------------
// erase/add tables, f32x2 math. 64 rows/block, 512 threads.
#define EA_ROWS 64
#define EA_SMEM_FLOATS (16384 + 16384 + EA_ROWS*DVz + 128 + 128)
__global__ void __launch_bounds__(512) k_ea(const float* __restrict__ qa_table,
                     const float* __restrict__ W_e, const float* __restrict__ b_e,
                     const float* __restrict__ W_a, const float* __restrict__ b_a) {
    extern __shared__ float sm[];
    float* We = sm;
    float* Wa = We + 16384;
    float* xs = Wa + 16384;
    float* be = xs + EA_ROWS * DVz;
    float* ba = be + 128;

    int tid = threadIdx.x;
    for (int i = tid; i < 4096; i += 512) {
        ((float4*)We)[i] = ((const float4*)W_e)[i];
        ((float4*)Wa)[i] = ((const float4*)W_a)[i];
    }
    if (tid < 128) { be[tid] = b_e[tid]; ba[tid] = b_a[tid]; }

    int row0 = blockIdx.x * EA_ROWS;
    for (int idx = tid; idx < EA_ROWS * 32; idx += 512) {
        int r = idx >> 5, c = idx & 31;
        int row = row0 + r;
        float4 v = make_float4(0.f, 0.f, 0.f, 0.f);
        if (row < NQA1) v = ((const float4*)(qa_table + (long)row * DVz))[c];
        ((float4*)xs)[r * 32 + c] = v;
    }
    __syncthreads();

    int rg = tid >> 4;
    int fg = tid & 15;
    u64 ae[2][4], aa[2][4];
#pragma unroll
    for (int r = 0; r < 2; r++)
#pragma unroll
        for (int j = 0; j < 4; j++) { ae[r][j] = 0ull; aa[r][j] = 0ull; }

#pragma unroll 4
    for (int k = 0; k < DVz; k++) {
        const ulonglong2* wep = (const ulonglong2*)(We + k * DVz + fg * 8);
        const ulonglong2* wap = (const ulonglong2*)(Wa + k * DVz + fg * 8);
        ulonglong2 e01 = wep[0], e23 = wep[1];
        ulonglong2 a01 = wap[0], a23 = wap[1];
#pragma unroll
        for (int r = 0; r < 2; r++) {
            float xv = xs[(rg * 2 + r) * DVz + k];
            u64 xp = pack2(xv, xv);
            ae[r][0] = fma2(xp, e01.x, ae[r][0]);
            ae[r][1] = fma2(xp, e01.y, ae[r][1]);
            ae[r][2] = fma2(xp, e23.x, ae[r][2]);
            ae[r][3] = fma2(xp, e23.y, ae[r][3]);
            aa[r][0] = fma2(xp, a01.x, aa[r][0]);
            aa[r][1] = fma2(xp, a01.y, aa[r][1]);
            aa[r][2] = fma2(xp, a23.x, aa[r][2]);
            aa[r][3] = fma2(xp, a23.y, aa[r][3]);
        }
    }

#pragma unroll
    for (int r = 0; r < 2; r++) {
        int row = row0 + rg * 2 + r;
        if (row < NQA1) {
            float er8[8], ad8[8];
#pragma unroll
            for (int j = 0; j < 4; j++) {
                int f = fg * 8 + 2 * j;
                float s0, s1, t0, t1;
                unpack2(ae[r][j], s0, s1);
                unpack2(aa[r][j], t0, t1);
                er8[2*j+0] = 1.0f / (1.0f + __expf(-(s0 + be[f])));
                er8[2*j+1] = 1.0f / (1.0f + __expf(-(s1 + be[f+1])));
                ad8[2*j+0] = tanhf(t0 + ba[f]);
                ad8[2*j+1] = tanhf(t1 + ba[f+1]);
            }
            float4* ep = (float4*)(g_er + (long)row * DVz + fg * 8);
            float4* ap = (float4*)(g_ad + (long)row * DVz + fg * 8);
            ep[0] = make_float4(er8[0], er8[1], er8[2], er8[3]);
            ep[1] = make_float4(er8[4], er8[5], er8[6], er8[7]);
            ap[0] = make_float4(ad8[0], ad8[1], ad8[2], ad8[3]);
            ap[1] = make_float4(ad8[4], ad8[5], ad8[6], ad8[7]);
        }
    }
}

// ---------------------------------------------------------------------------
// Scan: 256 blocks (one batch each) x 128 threads (one d-column each).
// Memory slots packed in PAIRS along M into f32x2: mem[25] u64 registers.
// Update (flag uniform-branch): mem += w * (a - e*mem)  => 2 fma2 per pair.
// Read: 25 fma2 into 4 chains, then lo+hi.
__global__ void __launch_bounds__(128) k_scan(const int* __restrict__ q_data,
                                              const int* __restrict__ qa_data,
                                              const float* __restrict__ init_value) {
    __shared__ u64 w_s[2][MP + 1];
    __shared__ int qi_s[Sz], qa_s[Sz];

    int b = blockIdx.x;
    int d = threadIdx.x;
    int base = b * Sz;

    for (int i = d; i < Sz; i += 128) {
        qi_s[i] = q_data[base + i];
        qa_s[i] = qa_data[base + i];
    }

    u64 mem[MP];
#pragma unroll
    for (int p = 0; p < MP; p++)
        mem[p] = pack2(init_value[(2*p) * DVz + d], init_value[(2*p+1) * DVz + d]);
    __syncthreads();

    // prime step 0: w pairs (threads 0..24), e/a for this d
    if (d < MP) {
        const float2* wp = (const float2*)(g_w + qi_s[0] * Mz);
        float2 v = wp[d];
        w_s[0][d] = pack2(v.x, v.y);
    }
    float en = g_er[qa_s[0] * DVz + d];
    float an = g_ad[qa_s[0] * DVz + d];
    __syncthreads();

    int buf = 0;
    for (int s = 0; s < Sz; s++) {
        float e = en, a = an;
        bool flag = (qi_s[s] >= 1);

        // prefetch next step
        if (s + 1 < Sz) {
            int qan = qa_s[s + 1];
            en = g_er[qan * DVz + d];
            an = g_ad[qan * DVz + d];
            if (d < MP) {
                const float2* wp = (const float2*)(g_w + qi_s[s + 1] * Mz);
                float2 v = wp[d];
                w_s[buf ^ 1][d] = pack2(v.x, v.y);
            }
        }

        u64 ne = pack2(e, e) ^ 0x8000000080000000ull;   // (-e, -e)
        u64 av = pack2(a, a);

        // read: both lanes accumulate partial sums over slot pairs
        u64 wr[MP];
        u64 r0 = 0ull, r1 = 0ull, r2 = 0ull, r3 = 0ull;
#pragma unroll
        for (int p = 0; p < 24; p += 4) {
            wr[p+0] = w_s[buf][p+0]; r0 = fma2(wr[p+0], mem[p+0], r0);
            wr[p+1] = w_s[buf][p+1]; r1 = fma2(wr[p+1], mem[p+1], r1);
            wr[p+2] = w_s[buf][p+2]; r2 = fma2(wr[p+2], mem[p+2], r2);
            wr[p+3] = w_s[buf][p+3]; r3 = fma2(wr[p+3], mem[p+3], r3);
        }
        wr[24] = w_s[buf][24]; r0 = fma2(wr[24], mem[24], r0);
        u64 rr = add2(add2(r0, r1), add2(r2, r3));
        float lo, hi;
        unpack2(rr, lo, hi);
        g_reads[(long)(base + s) * DVz + d] = lo + hi;

        // update owned slots (uniform branch per step)
        if (flag) {
#pragma unroll
            for (int p = 0; p < MP; p++) {
                u64 t = fma2(ne, mem[p], av);
                mem[p] = fma2(wr[p], t, mem[p]);
            }
        }

        __syncthreads();
        buf ^= 1;
    }
}

// ---------------------------------------------------------------------------
// Head: K=128 GEMM on reads; q-part gathered from g_qr in epilogue.
#define HD_ROWS 128
#define HEAD_SMEM_FLOATS (128*128 + HD_ROWS*128 + 128 + 128 + HD_ROWS + 2)
__global__ void __launch_bounds__(512) k_head(const int* __restrict__ q_data,
                       const float* __restrict__ target,
                       const float* __restrict__ W_read, const float* __restrict__ b_read,
                       const float* __restrict__ W_pred, const float* __restrict__ b_pred,
                       float* __restrict__ out) {
    extern __shared__ float sm[];
    float* Ws = sm;                   // 128 x 128 (rows 0..127 of W_read)
    float* xs = Ws + 128 * 128;       // 128 rows x 128
    float* br = xs + HD_ROWS * 128;
    float* wp = br + 128;
    float* lo = wp + 128;
    float* ls = lo + HD_ROWS;

    int tid = threadIdx.x;
    for (int i = tid; i < 128 * 128 / 4; i += 512)
        ((float4*)Ws)[i] = ((const float4*)W_read)[i];
    if (tid < 128) { br[tid] = b_read[tid]; wp[tid] = W_pred[tid]; }
    if (tid < 2)   ls[tid] = 0.0f;

    int row0 = blockIdx.x * HD_ROWS;
    for (int idx = tid; idx < HD_ROWS * 32; idx += 512) {
        int r = idx >> 5, c = idx & 31;
        int row = row0 + r;
        ((float4*)(xs + r * 128))[c] = ((const float4*)(g_reads + (long)row * DVz))[c];
    }
    __syncthreads();

    int rg = tid >> 4;  // 32 groups x 4 rows
    int fg = tid & 15;  // 8 f-cols (4 packed pairs)
    u64 acc[4][4];
#pragma unroll
    for (int r = 0; r < 4; r++)
#pragma unroll
        for (int j = 0; j < 4; j++) acc[r][j] = 0ull;

#pragma unroll 4
    for (int k = 0; k < 128; k++) {
        const ulonglong2* wv = (const ulonglong2*)(Ws + k * 128 + fg * 8);
        ulonglong2 w01 = wv[0], w23 = wv[1];
#pragma unroll
        for (int r = 0; r < 4; r++) {
            float xv = xs[(rg * 4 + r) * 128 + k];
            u64 xp = pack2(xv, xv);
            acc[r][0] = fma2(xp, w01.x, acc[r][0]);
            acc[r][1] = fma2(xp, w01.y, acc[r][1]);
            acc[r][2] = fma2(xp, w23.x, acc[r][2]);
            acc[r][3] = fma2(xp, w23.y, acc[r][3]);
        }
    }

    float bp = __ldg(b_pred);
#pragma unroll
    for (int r = 0; r < 4; r++) {
        int row = row0 + rg * 4 + r;
        int qi = q_data[row];
        const float4* qrp = (const float4*)(g_qr + (long)qi * Fz + fg * 8);
        float4 q0 = qrp[0], q1 = qrp[1];
        float qv[8] = {q0.x, q0.y, q0.z, q0.w, q1.x, q1.y, q1.z, q1.w};
        float p = 0.0f;
#pragma unroll
        for (int j = 0; j < 4; j++) {
            int f = fg * 8 + 2 * j;
            float s0, s1;
            unpack2(acc[r][j], s0, s1);
            p = fmaf(tanhf(s0 + qv[2*j]   + br[f]),     wp[f],     p);
            p = fmaf(tanhf(s1 + qv[2*j+1] + br[f + 1]), wp[f + 1], p);
        }
#pragma unroll
        for (int off = 8; off >= 1; off >>= 1)
            p += __shfl_down_sync(0xffffffffu, p, off, 16);
        if (fg == 0) lo[rg * 4 + r] = p + bp;
    }
    __syncthreads();

    if (tid < HD_ROWS) {
        int row = row0 + tid;
        float l = lo[tid];
        float prob = 1.0f / (1.0f + __expf(-l));
        out[1 + row] = prob;
        float t = target[row];
        float bce = 0.0f, cnt = 0.0f;
        if (t >= 0.0f) {
            bce = fmaxf(l, 0.0f) - l * t + log1pf(__expf(-fabsf(l)));
            cnt = 1.0f;
        }
#pragma unroll
        for (int off = 16; off >= 1; off >>= 1) {
            bce += __shfl_down_sync(0xffffffffu, bce, off);
            cnt += __shfl_down_sync(0xffffffffu, cnt, off);
        }
        if ((tid & 31) == 0) {
            atomicAdd(&ls[0], bce);
            atomicAdd(&ls[1], cnt);
        }
    }
    __syncthreads();
    if (tid == 0) {
        atomicAdd(&g_acc[0], ls[0]);
        atomicAdd(&g_acc[1], ls[1]);
    }
}

// ---------------------------------------------------------------------------
__global__ void k_fin(float* __restrict__ out) {
    out[0] = g_acc[0] / fmaxf(g_acc[1], 1.0f);
}

// ---------------------------------------------------------------------------
extern "C" void kernel_launch(void* const* d_in, const int* in_sizes, int n_in,
                              void* d_out, int out_size) {
    const int*   q_data    = (const int*)d_in[0];
    const int*   qa_data   = (const int*)d_in[1];
    const float* target    = (const float*)d_in[2];
    const float* q_table   = (const float*)d_in[3];
    const float* qa_table  = (const float*)d_in[4];
    const float* key_mem   = (const float*)d_in[5];
    const float* init_value= (const float*)d_in[6];
    const float* W_e    = (const float*)d_in[7];
    const float* b_e    = (const float*)d_in[8];
    const float* W_a    = (const float*)d_in[9];
    const float* b_a    = (const float*)d_in[10];
    const float* W_read = (const float*)d_in[11];
    const float* b_read = (const float*)d_in[12];
    const float* W_pred = (const float*)d_in[13];
    const float* b_pred = (const float*)d_in[14];
    float* out = (float*)d_out;

    cudaFuncSetAttribute(k_ea, cudaFuncAttributeMaxDynamicSharedMemorySize,
                         EA_SMEM_FLOATS * (int)sizeof(float));
    cudaFuncSetAttribute(k_head, cudaFuncAttributeMaxDynamicSharedMemorySize,
                         HEAD_SMEM_FLOATS * (int)sizeof(float));
    cudaFuncSetAttribute(k_qr, cudaFuncAttributeMaxDynamicSharedMemorySize,
                         QR_SMEM_FLOATS * (int)sizeof(float));

    k_init<<<1, 32>>>();
    k_w<<<(NQ1 + 127) / 128, 128>>>(q_table, key_mem);
    k_qr<<<(NQ1 + QR_ROWS - 1) / QR_ROWS, 512, QR_SMEM_FLOATS * sizeof(float)>>>(
        q_table, W_read);
    k_ea<<<(NQA1 + EA_ROWS - 1) / EA_ROWS, 512, EA_SMEM_FLOATS * sizeof(float)>>>(
        qa_table, W_e, b_e, W_a, b_a);
    k_scan<<<Bz, 128>>>(q_data, qa_data, init_value);
    k_head<<<NROWS / HD_ROWS, 512, HEAD_SMEM_FLOATS * sizeof(float)>>>(
        q_data, target, W_read, b_read, W_pred, b_pred, out);
    k_fin<<<1, 1>>>(out);
}

// round 5
// speedup vs baseline: 1.7867x; 1.0910x over previous
#include <cuda_runtime.h>
#include <math.h>

#define Bz 256
#define Sz 256
#define Mz 50
#define MP 25          // slot pairs
#define DQz 64
#define DVz 128
#define Fz 128
#define NQ1 10001
#define NQA1 20001
#define NROWS (Bz*Sz)

typedef unsigned long long u64;

// ---- packed f32x2 helpers (sm_103a FFMA2 path, PTX-only) -------------------
__device__ __forceinline__ u64 pack2(float lo, float hi) {
    u64 r; asm("mov.b64 %0, {%1, %2};" : "=l"(r) : "f"(lo), "f"(hi)); return r;
}
__device__ __forceinline__ void unpack2(u64 v, float& lo, float& hi) {
    asm("mov.b64 {%0, %1}, %2;" : "=f"(lo), "=f"(hi) : "l"(v));
}
__device__ __forceinline__ u64 fma2(u64 a, u64 b, u64 c) {
    u64 d; asm("fma.rn.f32x2 %0, %1, %2, %3;" : "=l"(d) : "l"(a), "l"(b), "l"(c)); return d;
}
__device__ __forceinline__ u64 add2(u64 a, u64 b) {
    u64 d; asm("add.rn.f32x2 %0, %1, %2;" : "=l"(d) : "l"(a), "l"(b)); return d;
}

// Scratch (static device globals — no allocation allowed)
__device__ float g_w[NQ1 * Mz];
__device__ float g_er[NQA1 * DVz];
__device__ float g_ad[NQA1 * DVz];
__device__ float g_qr[NQ1 * Fz];       // q_emb @ W_read[128:192] per unique q
__device__ float g_reads[NROWS * DVz];
__device__ float g_acc[2];

// ---------------------------------------------------------------------------
__global__ void k_init() {
    if (threadIdx.x < 2) g_acc[threadIdx.x] = 0.0f;
}

// ---------------------------------------------------------------------------
__global__ void k_w(const float* __restrict__ q_table,
                    const float* __restrict__ key_mem) {
    __shared__ float key_s[Mz * DQz];
    int tid = threadIdx.x;
    for (int i = tid; i < Mz * DQz; i += blockDim.x) key_s[i] = key_mem[i];
    __syncthreads();

    int row = blockIdx.x * 128 + tid;
    if (row >= NQ1) return;

    float q[DQz];
    const float4* qp = (const float4*)(q_table + row * DQz);
#pragma unroll
    for (int i = 0; i < DQz / 4; i++) {
        float4 v = qp[i];
        q[4*i+0] = v.x; q[4*i+1] = v.y; q[4*i+2] = v.z; q[4*i+3] = v.w;
    }

    float sc[Mz];
    float mx = -1e30f;
#pragma unroll
    for (int m = 0; m < Mz; m++) {
        float s = 0.0f;
#pragma unroll
        for (int k = 0; k < DQz; k++) s = fmaf(q[k], key_s[m * DQz + k], s);
        sc[m] = s;
        mx = fmaxf(mx, s);
    }
    float sum = 0.0f;
#pragma unroll
    for (int m = 0; m < Mz; m++) {
        float e = __expf(sc[m] - mx);
        sc[m] = e;
        sum += e;
    }
    float inv = 1.0f / sum;
#pragma unroll
    for (int m = 0; m < Mz; m++) g_w[row * Mz + m] = sc[m] * inv;
}

// ---------------------------------------------------------------------------
// q-part of the head: g_qr[i,:] = q_table[i,:] @ W_read[128:192,:]
#define QR_ROWS 64
#define QR_SMEM_FLOATS (64*128 + QR_ROWS*DQz)
__global__ void __launch_bounds__(512) k_qr(const float* __restrict__ q_table,
                                            const float* __restrict__ W_read) {
    extern __shared__ float sm[];
    float* W2 = sm;                  // 64 x 128 (rows 128..191 of W_read)
    float* xs = W2 + 64 * 128;       // 64 rows x 64

    int tid = threadIdx.x;
    for (int i = tid; i < 64 * 128 / 4; i += 512)
        ((float4*)W2)[i] = ((const float4*)(W_read + 128 * 128))[i];

    int row0 = blockIdx.x * QR_ROWS;
    for (int idx = tid; idx < QR_ROWS * 16; idx += 512) {
        int r = idx >> 4, c = idx & 15;
        int row = row0 + r;
        float4 v = make_float4(0.f, 0.f, 0.f, 0.f);
        if (row < NQ1) v = ((const float4*)(q_table + (long)row * DQz))[c];
        ((float4*)xs)[r * 16 + c] = v;
    }
    __syncthreads();

    int rg = tid >> 4;
    int fg = tid & 15;
    u64 acc[2][4];
#pragma unroll
    for (int r = 0; r < 2; r++)
#pragma unroll
        for (int j = 0; j < 4; j++) acc[r][j] = 0ull;

#pragma unroll 4
    for (int k = 0; k < 64; k++) {
        const ulonglong2* wv = (const ulonglong2*)(W2 + k * 128 + fg * 8);
        ulonglong2 w01 = wv[0], w23 = wv[1];
#pragma unroll
        for (int r = 0; r < 2; r++) {
            float xv = xs[(rg * 2 + r) * DQz + k];
            u64 xp = pack2(xv, xv);
            acc[r][0] = fma2(xp, w01.x, acc[r][0]);
            acc[r][1] = fma2(xp, w01.y, acc[r][1]);
            acc[r][2] = fma2(xp, w23.x, acc[r][2]);
            acc[r][3] = fma2(xp, w23.y, acc[r][3]);
        }
    }

#pragma unroll
    for (int r = 0; r < 2; r++) {
        int row = row0 + rg * 2 + r;
        if (row < NQ1) {
            float v[8];
#pragma unroll
            for (int j = 0; j < 4; j++) unpack2(acc[r][j], v[2*j], v[2*j+1]);
            float4* op = (float4*)(g_qr + (long)row * Fz + fg * 8);
            op[0] = make_float4(v[0], v[1], v[2], v[3]);
            op[1] = make_float4(v[4], v[5], v[6], v[7]);
        }
    }
}

// ---------------------------------------------------------------------------
// erase/add tables, f32x2, 4 rows/thread (weight LDS amortized 2x vs R4).
#define EA_ROWS 128
#define EA_SMEM_FLOATS (16384 + 16384 + EA_ROWS*DVz + 128 + 128)
__global__ void __launch_bounds__(512) k_ea(const float* __restrict__ qa_table,
                     const float* __restrict__ W_e, const float* __restrict__ b_e,
                     const float* __restrict__ W_a, const float* __restrict__ b_a) {
    extern __shared__ float sm[];
    float* We = sm;
    float* Wa = We + 16384;
    float* xs = Wa + 16384;
    float* be = xs + EA_ROWS * DVz;
    float* ba = be + 128;

    int tid = threadIdx.x;
    for (int i = tid; i < 4096; i += 512) {
        ((float4*)We)[i] = ((const float4*)W_e)[i];
        ((float4*)Wa)[i] = ((const float4*)W_a)[i];
    }
    if (tid < 128) { be[tid] = b_e[tid]; ba[tid] = b_a[tid]; }

    int row0 = blockIdx.x * EA_ROWS;
    for (int idx = tid; idx < EA_ROWS * 32; idx += 512) {
        int r = idx >> 5, c = idx & 31;
        int row = row0 + r;
        float4 v = make_float4(0.f, 0.f, 0.f, 0.f);
        if (row < NQA1) v = ((const float4*)(qa_table + (long)row * DVz))[c];
        ((float4*)xs)[r * 32 + c] = v;
    }
    __syncthreads();

    int rg = tid >> 4;   // 32 groups of 4 rows
    int fg = tid & 15;   // 8 output cols (4 packed pairs)
    u64 ae[4][4], aa[4][4];
#pragma unroll
    for (int r = 0; r < 4; r++)
#pragma unroll
        for (int j = 0; j < 4; j++) { ae[r][j] = 0ull; aa[r][j] = 0ull; }

#pragma unroll 2
    for (int k = 0; k < DVz; k++) {
        const ulonglong2* wep = (const ulonglong2*)(We + k * DVz + fg * 8);
        const ulonglong2* wap = (const ulonglong2*)(Wa + k * DVz + fg * 8);
        ulonglong2 e01 = wep[0], e23 = wep[1];
        ulonglong2 a01 = wap[0], a23 = wap[1];
#pragma unroll
        for (int r = 0; r < 4; r++) {
            float xv = xs[(rg * 4 + r) * DVz + k];
            u64 xp = pack2(xv, xv);
            ae[r][0] = fma2(xp, e01.x, ae[r][0]);
            ae[r][1] = fma2(xp, e01.y, ae[r][1]);
            ae[r][2] = fma2(xp, e23.x, ae[r][2]);
            ae[r][3] = fma2(xp, e23.y, ae[r][3]);
            aa[r][0] = fma2(xp, a01.x, aa[r][0]);
            aa[r][1] = fma2(xp, a01.y, aa[r][1]);
            aa[r][2] = fma2(xp, a23.x, aa[r][2]);
            aa[r][3] = fma2(xp, a23.y, aa[r][3]);
        }
    }

#pragma unroll
    for (int r = 0; r < 4; r++) {
        int row = row0 + rg * 4 + r;
        if (row < NQA1) {
            float er8[8], ad8[8];
#pragma unroll
            for (int j = 0; j < 4; j++) {
                int f = fg * 8 + 2 * j;
                float s0, s1, t0, t1;
                unpack2(ae[r][j], s0, s1);
                unpack2(aa[r][j], t0, t1);
                er8[2*j+0] = 1.0f / (1.0f + __expf(-(s0 + be[f])));
                er8[2*j+1] = 1.0f / (1.0f + __expf(-(s1 + be[f+1])));
                ad8[2*j+0] = tanhf(t0 + ba[f]);
                ad8[2*j+1] = tanhf(t1 + ba[f+1]);
            }
            float4* ep = (float4*)(g_er + (long)row * DVz + fg * 8);
            float4* ap = (float4*)(g_ad + (long)row * DVz + fg * 8);
            ep[0] = make_float4(er8[0], er8[1], er8[2], er8[3]);
            ep[1] = make_float4(er8[4], er8[5], er8[6], er8[7]);
            ap[0] = make_float4(ad8[0], ad8[1], ad8[2], ad8[3]);
            ap[1] = make_float4(ad8[4], ad8[5], ad8[6], ad8[7]);
        }
    }
}

// ---------------------------------------------------------------------------
// Scan: 128 blocks x 256 threads. Each block runs 2 batches (one per
// thread-half). NO block barrier in the hot loop: each warp stages its own
// w copy (lanes 0..24) into private smem, synced with __syncwarp only.
// Slots packed in pairs along M (f32x2). 128 blocks <= 148 SMs: one wave.
__global__ void __launch_bounds__(256) k_scan(const int* __restrict__ q_data,
                                              const int* __restrict__ qa_data,
                                              const float* __restrict__ init_value) {
    __shared__ u64 w_s[8][2][MP + 1];   // per-warp double-buffered w
    __shared__ int qi_s[2][Sz], qa_s[2][Sz];

    int tid  = threadIdx.x;
    int half = tid >> 7;        // batch selector within block
    int d    = tid & 127;       // DV column
    int warp = tid >> 5;
    int lane = tid & 31;

    int b = blockIdx.x * 2 + half;
    int base = b * Sz;

    for (int i = d; i < Sz; i += 128) {
        qi_s[half][i] = q_data[base + i];
        qa_s[half][i] = qa_data[base + i];
    }

    u64 mem[MP];
#pragma unroll
    for (int p = 0; p < MP; p++)
        mem[p] = pack2(init_value[(2*p) * DVz + d], init_value[(2*p+1) * DVz + d]);
    __syncthreads();   // indices staged (once)

    // prime step 0 per warp
    if (lane < MP) {
        const float2* wp = (const float2*)(g_w + qi_s[half][0] * Mz);
        float2 v = wp[lane];
        w_s[warp][0][lane] = pack2(v.x, v.y);
    }
    float en = g_er[qa_s[half][0] * DVz + d];
    float an = g_ad[qa_s[half][0] * DVz + d];
    __syncwarp();

    int buf = 0;
    for (int s = 0; s < Sz; s++) {
        float e = en, a = an;
        bool flag = (qi_s[half][s] >= 1);

        // prefetch next step (per-warp, decoupled)
        if (s + 1 < Sz) {
            int qan = qa_s[half][s + 1];
            en = g_er[qan * DVz + d];
            an = g_ad[qan * DVz + d];
            if (lane < MP) {
                const float2* wp = (const float2*)(g_w + qi_s[half][s + 1] * Mz);
                float2 v = wp[lane];
                w_s[warp][buf ^ 1][lane] = pack2(v.x, v.y);
            }
        }

        u64 ne = pack2(e, e) ^ 0x8000000080000000ull;   // (-e, -e)
        u64 av = pack2(a, a);

        // read: r[d] = sum over slot pairs
        u64 wr[MP];
        u64 r0 = 0ull, r1 = 0ull, r2 = 0ull, r3 = 0ull;
#pragma unroll
        for (int p = 0; p < 24; p += 4) {
            wr[p+0] = w_s[warp][buf][p+0]; r0 = fma2(wr[p+0], mem[p+0], r0);
            wr[p+1] = w_s[warp][buf][p+1]; r1 = fma2(wr[p+1], mem[p+1], r1);
            wr[p+2] = w_s[warp][buf][p+2]; r2 = fma2(wr[p+2], mem[p+2], r2);
            wr[p+3] = w_s[warp][buf][p+3]; r3 = fma2(wr[p+3], mem[p+3], r3);
        }
        wr[24] = w_s[warp][buf][24]; r0 = fma2(wr[24], mem[24], r0);
        u64 rr = add2(add2(r0, r1), add2(r2, r3));
        float lo, hi;
        unpack2(rr, lo, hi);
        g_reads[(long)(base + s) * DVz + d] = lo + hi;

        // update (uniform branch per warp: all lanes same batch)
        if (flag) {
#pragma unroll
            for (int p = 0; p < MP; p++) {
                u64 t = fma2(ne, mem[p], av);
                mem[p] = fma2(wr[p], t, mem[p]);
            }
        }

        __syncwarp();
        buf ^= 1;
    }
}

// ---------------------------------------------------------------------------
// Head: K=128 GEMM on reads (8 rows/thread), q-part gathered from g_qr.
#define HD_ROWS 256
#define HEAD_SMEM_FLOATS (128*128 + HD_ROWS*128 + 128 + 128 + HD_ROWS + 2)
__global__ void __launch_bounds__(512) k_head(const int* __restrict__ q_data,
                       const float* __restrict__ target,
                       const float* __restrict__ W_read, const float* __restrict__ b_read,
                       const float* __restrict__ W_pred, const float* __restrict__ b_pred,
                       float* __restrict__ out) {
    extern __shared__ float sm[];
    float* Ws = sm;                   // 128 x 128
    float* xs = Ws + 128 * 128;       // 256 rows x 128
    float* br = xs + HD_ROWS * 128;
    float* wp = br + 128;
    float* lo = wp + 128;
    float* ls = lo + HD_ROWS;

    int tid = threadIdx.x;
    for (int i = tid; i < 128 * 128 / 4; i += 512)
        ((float4*)Ws)[i] = ((const float4*)W_read)[i];
    if (tid < 128) { br[tid] = b_read[tid]; wp[tid] = W_pred[tid]; }
    if (tid < 2)   ls[tid] = 0.0f;

    int row0 = blockIdx.x * HD_ROWS;
    for (int idx = tid; idx < HD_ROWS * 32; idx += 512) {
        int r = idx >> 5, c = idx & 31;
        int row = row0 + r;
        ((float4*)(xs + r * 128))[c] = ((const float4*)(g_reads + (long)row * DVz))[c];
    }
    __syncthreads();

    int rg = tid >> 4;  // 32 groups x 8 rows
    int fg = tid & 15;  // 8 f-cols (4 packed pairs)
    u64 acc[8][4];
#pragma unroll
    for (int r = 0; r < 8; r++)
#pragma unroll
        for (int j = 0; j < 4; j++) acc[r][j] = 0ull;

#pragma unroll 2
    for (int k = 0; k < 128; k++) {
        const ulonglong2* wv = (const ulonglong2*)(Ws + k * 128 + fg * 8);
        ulonglong2 w01 = wv[0], w23 = wv[1];
#pragma unroll
        for (int r = 0; r < 8; r++) {
            float xv = xs[(rg * 8 + r) * 128 + k];
            u64 xp = pack2(xv, xv);
            acc[r][0] = fma2(xp, w01.x, acc[r][0]);
            acc[r][1] = fma2(xp, w01.y, acc[r][1]);
            acc[r][2] = fma2(xp, w23.x, acc[r][2]);
            acc[r][3] = fma2(xp, w23.y, acc[r][3]);
        }
    }

    float bp = __ldg(b_pred);
#pragma unroll
    for (int r = 0; r < 8; r++) {
        int row = row0 + rg * 8 + r;
        int qi = q_data[row];
        const float4* qrp = (const float4*)(g_qr + (long)qi * Fz + fg * 8);
        float4 q0 = qrp[0], q1 = qrp[1];
        float qv[8] = {q0.x, q0.y, q0.z, q0.w, q1.x, q1.y, q1.z, q1.w};
        float p = 0.0f;
#pragma unroll
        for (int j = 0; j < 4; j++) {
            int f = fg * 8 + 2 * j;
            float s0, s1;
            unpack2(acc[r][j], s0, s1);
            p = fmaf(tanhf(s0 + qv[2*j]   + br[f]),     wp[f],     p);
            p = fmaf(tanhf(s1 + qv[2*j+1] + br[f + 1]), wp[f + 1], p);
        }
#pragma unroll
        for (int off = 8; off >= 1; off >>= 1)
            p += __shfl_down_sync(0xffffffffu, p, off, 16);
        if (fg == 0) lo[rg * 8 + r] = p + bp;
    }
    __syncthreads();

    for (int t = tid; t < HD_ROWS; t += 512) {
        int row = row0 + t;
        float l = lo[t];
        float prob = 1.0f / (1.0f + __expf(-l));
        out[1 + row] = prob;
        float tt = target[row];
        float bce = 0.0f, cnt = 0.0f;
        if (tt >= 0.0f) {
            bce = fmaxf(l, 0.0f) - l * tt + log1pf(__expf(-fabsf(l)));
            cnt = 1.0f;
        }
#pragma unroll
        for (int off = 16; off >= 1; off >>= 1) {
            bce += __shfl_down_sync(0xffffffffu, bce, off);
            cnt += __shfl_down_sync(0xffffffffu, cnt, off);
        }
        if ((tid & 31) == 0) {
            atomicAdd(&ls[0], bce);
            atomicAdd(&ls[1], cnt);
        }
    }
    __syncthreads();
    if (tid == 0) {
        atomicAdd(&g_acc[0], ls[0]);
        atomicAdd(&g_acc[1], ls[1]);
    }
}

// ---------------------------------------------------------------------------
__global__ void k_fin(float* __restrict__ out) {
    out[0] = g_acc[0] / fmaxf(g_acc[1], 1.0f);
}

// ---------------------------------------------------------------------------
extern "C" void kernel_launch(void* const* d_in, const int* in_sizes, int n_in,
                              void* d_out, int out_size) {
    const int*   q_data    = (const int*)d_in[0];
    const int*   qa_data   = (const int*)d_in[1];
    const float* target    = (const float*)d_in[2];
    const float* q_table   = (const float*)d_in[3];
    const float* qa_table  = (const float*)d_in[4];
    const float* key_mem   = (const float*)d_in[5];
    const float* init_value= (const float*)d_in[6];
    const float* W_e    = (const float*)d_in[7];
    const float* b_e    = (const float*)d_in[8];
    const float* W_a    = (const float*)d_in[9];
    const float* b_a    = (const float*)d_in[10];
    const float* W_read = (const float*)d_in[11];
    const float* b_read = (const float*)d_in[12];
    const float* W_pred = (const float*)d_in[13];
    const float* b_pred = (const float*)d_in[14];
    float* out = (float*)d_out;

    cudaFuncSetAttribute(k_ea, cudaFuncAttributeMaxDynamicSharedMemorySize,
                         EA_SMEM_FLOATS * (int)sizeof(float));
    cudaFuncSetAttribute(k_head, cudaFuncAttributeMaxDynamicSharedMemorySize,
                         HEAD_SMEM_FLOATS * (int)sizeof(float));
    cudaFuncSetAttribute(k_qr, cudaFuncAttributeMaxDynamicSharedMemorySize,
                         QR_SMEM_FLOATS * (int)sizeof(float));

    k_init<<<1, 32>>>();
    k_w<<<(NQ1 + 127) / 128, 128>>>(q_table, key_mem);
    k_qr<<<(NQ1 + QR_ROWS - 1) / QR_ROWS, 512, QR_SMEM_FLOATS * sizeof(float)>>>(
        q_table, W_read);
    k_ea<<<(NQA1 + EA_ROWS - 1) / EA_ROWS, 512, EA_SMEM_FLOATS * sizeof(float)>>>(
        qa_table, W_e, b_e, W_a, b_a);
    k_scan<<<Bz / 2, 256>>>(q_data, qa_data, init_value);
    k_head<<<NROWS / HD_ROWS, 512, HEAD_SMEM_FLOATS * sizeof(float)>>>(
        q_data, target, W_read, b_read, W_pred, b_pred, out);
    k_fin<<<1, 1>>>(out);
}